// round 1
// baseline (speedup 1.0000x reference)
#include <cuda_runtime.h>
#include <math.h>

// Problem constants
#define B_      32
#define T_      1024
#define INCH    3
#define NG      2
#define CD      12          // path channels: 1 time + 3 orig + 8 aug
#define SIGC    1884        // 12 + 144 + 1728
#define NBG     64          // B * G paths
#define NCHUNK  16
#define CH_STEPS 64
#define NSTEPS  1023
#define DT_     (1.0f/1023.0f)

// Scratch (static device arrays — no allocation)
__device__ __align__(16) float g_chunksig[NBG * NCHUNK * SIGC];  // ~7.7 MB
__device__ __align__(16) float g_sig[NBG * SIGC];                // ~482 KB

// ---------------------------------------------------------------------------
// Kernel 1: per-chunk truncated signature (depth 3) via the collapsed update:
//   S3[i][j][k] += (S2[i][j] + (S1[i] + d_i/3) * d_j * 0.5) * d_k
//   S2[i][j]    += (S1[i] + d_i/2) * d_j
//   S1[i]       += d_i
// Thread tid<144 owns pair (i,j) = (tid/12, tid%12): 12 S3 regs + s2 + s1.
// ---------------------------------------------------------------------------
__global__ __launch_bounds__(160) void sig_chunk_kernel(
    const float* __restrict__ x, const float* __restrict__ aug_w)
{
    int chunk = blockIdx.x;          // 0..1023
    int bg = chunk >> 4;             // path id (b*2+g)
    int c  = chunk & 15;             // chunk index within path
    int b  = bg >> 1;
    int g  = bg & 1;
    int t0 = c * CH_STEPS;
    int L  = min(CH_STEPS, NSTEPS - t0);   // 64, last chunk 63

    __shared__ __align__(16) float sh_d[CH_STEPS * CD];
    __shared__ float sh_w[24];

    int tid = threadIdx.x;
    if (tid < 24) sh_w[tid] = aug_w[g * 24 + tid];
    __syncthreads();

    // Precompute increments for this chunk: d[t] = [dt, dx0..2, W_g*dx]
    if (tid < L) {
        const float* xp = x + ((size_t)b * T_ + (t0 + tid)) * INCH;
        float dx0 = xp[3] - xp[0];
        float dx1 = xp[4] - xp[1];
        float dx2 = xp[5] - xp[2];
        float* dr = sh_d + tid * CD;
        dr[0] = DT_; dr[1] = dx0; dr[2] = dx1; dr[3] = dx2;
#pragma unroll
        for (int e = 0; e < 8; e++)
            dr[4 + e] = sh_w[e*3]*dx0 + sh_w[e*3+1]*dx1 + sh_w[e*3+2]*dx2;
    }
    __syncthreads();

    if (tid >= 144) return;
    int i = tid / 12;
    int j = tid % 12;

    float s1 = 0.f, s2 = 0.f;
    float s3[12];
#pragma unroll
    for (int k = 0; k < 12; k++) s3[k] = 0.f;

    for (int t = 0; t < L; t++) {
        const float* dr = sh_d + t * CD;
        float4 d0 = *(const float4*)(dr);
        float4 d1 = *(const float4*)(dr + 4);
        float4 d2 = *(const float4*)(dr + 8);
        float di = dr[i];
        float dj = dr[j];
        // coefficient for S3 row update (uses OLD s1, s2)
        float c3 = fmaf(fmaf(di, (1.f/3.f), s1), 0.5f * dj, s2);
        s3[0]  = fmaf(c3, d0.x, s3[0]);  s3[1]  = fmaf(c3, d0.y, s3[1]);
        s3[2]  = fmaf(c3, d0.z, s3[2]);  s3[3]  = fmaf(c3, d0.w, s3[3]);
        s3[4]  = fmaf(c3, d1.x, s3[4]);  s3[5]  = fmaf(c3, d1.y, s3[5]);
        s3[6]  = fmaf(c3, d1.z, s3[6]);  s3[7]  = fmaf(c3, d1.w, s3[7]);
        s3[8]  = fmaf(c3, d2.x, s3[8]);  s3[9]  = fmaf(c3, d2.y, s3[9]);
        s3[10] = fmaf(c3, d2.z, s3[10]); s3[11] = fmaf(c3, d2.w, s3[11]);
        s2 = fmaf(fmaf(di, 0.5f, s1), dj, s2);
        s1 += di;
    }

    // Store chunk signature: [S1(12) | S2(144) | S3(1728)] signatory layout
    float* out = g_chunksig + (size_t)chunk * SIGC;
    if (j == 0) out[i] = s1;
    out[12 + tid] = s2;
    float* o3 = out + 156 + tid * 12;
    *(float4*)(o3)     = make_float4(s3[0], s3[1], s3[2], s3[3]);
    *(float4*)(o3 + 4) = make_float4(s3[4], s3[5], s3[6], s3[7]);
    *(float4*)(o3 + 8) = make_float4(s3[8], s3[9], s3[10], s3[11]);
}

// ---------------------------------------------------------------------------
// Kernel 2: Chen combine of 16 chunk signatures per path (left-to-right):
//   C3 = A3 + B3 + A1 (x) B2 + A2 (x) B1
//   C2 = A2 + B2 + A1 (x) B1
//   C1 = A1 + B1
// ---------------------------------------------------------------------------
__global__ __launch_bounds__(160) void sig_combine_kernel()
{
    int bg  = blockIdx.x;
    int tid = threadIdx.x;
    if (tid >= 144) return;
    int i = tid / 12;
    int j = tid % 12;

    const float* base = g_chunksig + (size_t)bg * NCHUNK * SIGC;

    float a1 = base[i];
    float a2 = base[12 + tid];
    float a3[12];
    {
        const float* p = base + 156 + tid * 12;
        float4 v0 = *(const float4*)p;
        float4 v1 = *(const float4*)(p + 4);
        float4 v2 = *(const float4*)(p + 8);
        a3[0]=v0.x; a3[1]=v0.y; a3[2]=v0.z;  a3[3]=v0.w;
        a3[4]=v1.x; a3[5]=v1.y; a3[6]=v1.z;  a3[7]=v1.w;
        a3[8]=v2.x; a3[9]=v2.y; a3[10]=v2.z; a3[11]=v2.w;
    }

    for (int c = 1; c < NCHUNK; c++) {
        const float* Bp = base + (size_t)c * SIGC;
        float4 b1a = *(const float4*)(Bp);
        float4 b1b = *(const float4*)(Bp + 4);
        float4 b1c = *(const float4*)(Bp + 8);
        float b1i = Bp[i];
        float b1j = Bp[j];
        float b2s = Bp[12 + tid];
        const float* r2 = Bp + 12 + j * 12;          // B2 row j
        float4 r2a = *(const float4*)(r2);
        float4 r2b = *(const float4*)(r2 + 4);
        float4 r2c = *(const float4*)(r2 + 8);
        const float* p3 = Bp + 156 + tid * 12;
        float4 b3a = *(const float4*)(p3);
        float4 b3b = *(const float4*)(p3 + 4);
        float4 b3c = *(const float4*)(p3 + 8);

        a3[0]  += b3a.x + a1*r2a.x + a2*b1a.x;
        a3[1]  += b3a.y + a1*r2a.y + a2*b1a.y;
        a3[2]  += b3a.z + a1*r2a.z + a2*b1a.z;
        a3[3]  += b3a.w + a1*r2a.w + a2*b1a.w;
        a3[4]  += b3b.x + a1*r2b.x + a2*b1b.x;
        a3[5]  += b3b.y + a1*r2b.y + a2*b1b.y;
        a3[6]  += b3b.z + a1*r2b.z + a2*b1b.z;
        a3[7]  += b3b.w + a1*r2b.w + a2*b1b.w;
        a3[8]  += b3c.x + a1*r2c.x + a2*b1c.x;
        a3[9]  += b3c.y + a1*r2c.y + a2*b1c.y;
        a3[10] += b3c.z + a1*r2c.z + a2*b1c.z;
        a3[11] += b3c.w + a1*r2c.w + a2*b1c.w;
        a2 += b2s + a1 * b1j;     // uses OLD a1
        a1 += b1i;
    }

    float* out = g_sig + (size_t)bg * SIGC;
    if (j == 0) out[i] = a1;
    out[12 + tid] = a2;
    float* o3 = out + 156 + tid * 12;
    *(float4*)(o3)     = make_float4(a3[0], a3[1], a3[2], a3[3]);
    *(float4*)(o3 + 4) = make_float4(a3[4], a3[5], a3[6], a3[7]);
    *(float4*)(o3 + 8) = make_float4(a3[8], a3[9], a3[10], a3[11]);
}

// ---------------------------------------------------------------------------
// Kernel 3: out[b][o] = sigmoid( sig[b] . lin_w[o] + lin_b[o] )
// sig[b] = concat over g (contiguous in g_sig since bg = b*2+g).
// ---------------------------------------------------------------------------
__global__ __launch_bounds__(256) void sig_out_kernel(
    const float* __restrict__ lin_w, const float* __restrict__ lin_b,
    float* __restrict__ out)
{
    int b = blockIdx.x;
    __shared__ float sh[2 * SIGC];
    const float* sig = g_sig + (size_t)b * 2 * SIGC;
    for (int idx = threadIdx.x; idx < 2 * SIGC; idx += blockDim.x)
        sh[idx] = sig[idx];
    __syncthreads();

    int warp = threadIdx.x >> 5;
    int lane = threadIdx.x & 31;
    for (int o = warp; o < 32; o += 8) {
        const float* wr = lin_w + (size_t)o * 2 * SIGC;
        float acc = 0.f;
        for (int idx = lane; idx < 2 * SIGC; idx += 32)
            acc = fmaf(wr[idx], sh[idx], acc);
#pragma unroll
        for (int off = 16; off; off >>= 1)
            acc += __shfl_down_sync(0xffffffffu, acc, off);
        if (lane == 0) {
            float z = acc + lin_b[o];
            out[b * 32 + o] = 1.0f / (1.0f + expf(-z));
        }
    }
}

// ---------------------------------------------------------------------------
extern "C" void kernel_launch(void* const* d_in, const int* in_sizes, int n_in,
                              void* d_out, int out_size)
{
    const float* x     = (const float*)d_in[0];  // (32,1024,3)
    const float* aug_w = (const float*)d_in[1];  // (2,8,3)
    // d_in[2] = aug_b — unused (bias cancels in path increments)
    const float* lin_w = (const float*)d_in[3];  // (32, 3768)
    const float* lin_b = (const float*)d_in[4];  // (32,)
    float* out = (float*)d_out;                  // (32,32)

    sig_chunk_kernel<<<NBG * NCHUNK, 160>>>(x, aug_w);
    sig_combine_kernel<<<NBG, 160>>>();
    sig_out_kernel<<<B_, 256>>>(lin_w, lin_b, out);
}

// round 5
// speedup vs baseline: 1.2791x; 1.2791x over previous
#include <cuda_runtime.h>
#include <math.h>

// Problem constants
#define B_      32
#define T_      1024
#define INCH    3
#define CD      12          // path channels: 1 time + 3 orig + 8 aug
#define SIGC    1884        // 12 + 144 + 1728
#define NBG     64          // B * G paths
#define NCHUNK  16
#define CH_STEPS 64
#define NSTEPS  1023
#define DT_     (1.0f/1023.0f)
#define CPB     2           // chunks per block in kernel 1

// Scratch (static device arrays — no allocation)
__device__ __align__(16) float g_chunksig[NBG * NCHUNK * SIGC];  // ~7.7 MB
__device__ __align__(16) float g_mid[NBG * 4 * SIGC];            // ~1.9 MB
__device__ __align__(16) float g_sig[NBG * SIGC];                // ~482 KB

typedef unsigned long long ull;

__device__ __forceinline__ ull pack2(float a, float b) {
    ull r;
    asm("mov.b64 %0, {%1,%2};" : "=l"(r) : "f"(a), "f"(b));
    return r;
}
__device__ __forceinline__ void ffma2(ull& d, ull a, ull b) {
    asm("fma.rn.f32x2 %0, %1, %2, %0;" : "+l"(d) : "l"(a), "l"(b));
}
union U64F2 { ull u; float2 f; };

// ---------------------------------------------------------------------------
// Kernel 1: per-chunk depth-3 signature. Collapsed per-step update:
//   S3[i][j][:] += (S2[i][j] + (S1[i] + d_i/3) * d_j/2) * d[:]   (6x FFMA2)
//   S2[i][j]    += (S1[i] + d_i/2) * d_j
//   S1[i]       += d_i
// 288 threads = 2 chunks x 144 (i,j) pairs, 9 full warps.
// ---------------------------------------------------------------------------
__global__ __launch_bounds__(288) void sig_chunk_kernel(
    const float* __restrict__ x, const float* __restrict__ aug_w)
{
    __shared__ __align__(16) float sh_d[CPB][CH_STEPS * CD];
    __shared__ float sh_w[CPB][24];

    int tid = threadIdx.x;
    int sub = (tid >= 144) ? 1 : 0;
    int wt  = tid - sub * 144;              // 0..143
    int chunk = blockIdx.x * CPB + sub;     // 0..1023
    int bg = chunk >> 4;                    // path id (b*2+g)
    int c  = chunk & 15;
    int b  = bg >> 1;
    int g  = bg & 1;
    int t0 = c * CH_STEPS;
    int L  = min(CH_STEPS, NSTEPS - t0);    // 64, last chunk per path 63

    if (wt < 24) sh_w[sub][wt] = aug_w[g * 24 + wt];
    __syncthreads();

    // increments: d[t] = [dt, dx0..2, W_g*dx]  (aug bias cancels)
    if (wt < L) {
        const float* xp = x + ((size_t)b * T_ + (t0 + wt)) * INCH;
        float dx0 = xp[3] - xp[0];
        float dx1 = xp[4] - xp[1];
        float dx2 = xp[5] - xp[2];
        float* dr = sh_d[sub] + wt * CD;
        dr[0] = DT_; dr[1] = dx0; dr[2] = dx1; dr[3] = dx2;
        const float* w = sh_w[sub];
#pragma unroll
        for (int e = 0; e < 8; e++)
            dr[4 + e] = w[e*3]*dx0 + w[e*3+1]*dx1 + w[e*3+2]*dx2;
    }
    __syncthreads();

    int i = wt / 12;
    int j = wt % 12;

    float s1 = 0.f, s2 = 0.f;
    ull s3p[6];
#pragma unroll
    for (int m = 0; m < 6; m++) s3p[m] = 0ull;

    const float* drbase = sh_d[sub];
#pragma unroll 4
    for (int t = 0; t < L; t++) {
        const float* dr = drbase + t * CD;
        const ulonglong2* q = (const ulonglong2*)dr;   // 16B-aligned (48B rows)
        ulonglong2 qa = q[0];
        ulonglong2 qb = q[1];
        ulonglong2 qc = q[2];
        float di = dr[i];
        float dj = dr[j];
        float c3 = fmaf(fmaf(di, (1.f/3.f), s1), 0.5f * dj, s2);
        ull cc = pack2(c3, c3);
        ffma2(s3p[0], cc, qa.x); ffma2(s3p[1], cc, qa.y);
        ffma2(s3p[2], cc, qb.x); ffma2(s3p[3], cc, qb.y);
        ffma2(s3p[4], cc, qc.x); ffma2(s3p[5], cc, qc.y);
        s2 = fmaf(fmaf(di, 0.5f, s1), dj, s2);
        s1 += di;
    }

    // Store chunk signature: [S1(12) | S2(144) | S3(1728)] signatory layout
    float* out = g_chunksig + (size_t)chunk * SIGC;
    if (j == 0) out[i] = s1;
    out[12 + wt] = s2;
    float* o3 = out + 156 + wt * 12;
    U64F2 u0, u1, u2, u3, u4, u5;
    u0.u = s3p[0]; u1.u = s3p[1]; u2.u = s3p[2];
    u3.u = s3p[3]; u4.u = s3p[4]; u5.u = s3p[5];
    *(float4*)(o3)     = make_float4(u0.f.x, u0.f.y, u1.f.x, u1.f.y);
    *(float4*)(o3 + 4) = make_float4(u2.f.x, u2.f.y, u3.f.x, u3.f.y);
    *(float4*)(o3 + 8) = make_float4(u4.f.x, u4.f.y, u5.f.x, u5.f.y);
}

// ---------------------------------------------------------------------------
// Chen combine of `nmerge` consecutive signatures (left-to-right):
//   C3 = A3 + B3 + A1 (x) B2 + A2 (x) B1 ; C2 = A2 + B2 + A1 (x) B1 ; C1 = A1+B1
// ---------------------------------------------------------------------------
__device__ __forceinline__ void combine_path(
    const float* __restrict__ base, float* __restrict__ out, int nmerge, int tid)
{
    int i = tid / 12;
    int j = tid % 12;

    float a1 = base[i];
    float a2 = base[12 + tid];
    float a3[12];
    {
        const float* p = base + 156 + tid * 12;
        float4 v0 = *(const float4*)p;
        float4 v1 = *(const float4*)(p + 4);
        float4 v2 = *(const float4*)(p + 8);
        a3[0]=v0.x; a3[1]=v0.y; a3[2]=v0.z;  a3[3]=v0.w;
        a3[4]=v1.x; a3[5]=v1.y; a3[6]=v1.z;  a3[7]=v1.w;
        a3[8]=v2.x; a3[9]=v2.y; a3[10]=v2.z; a3[11]=v2.w;
    }

    for (int c = 1; c < nmerge; c++) {
        const float* Bp = base + (size_t)c * SIGC;
        float4 b1a = *(const float4*)(Bp);
        float4 b1b = *(const float4*)(Bp + 4);
        float4 b1c = *(const float4*)(Bp + 8);
        float b1i = Bp[i];
        float b1j = Bp[j];
        float b2s = Bp[12 + tid];
        const float* r2 = Bp + 12 + j * 12;          // B2 row j
        float4 r2a = *(const float4*)(r2);
        float4 r2b = *(const float4*)(r2 + 4);
        float4 r2c = *(const float4*)(r2 + 8);
        const float* p3 = Bp + 156 + tid * 12;
        float4 b3a = *(const float4*)(p3);
        float4 b3b = *(const float4*)(p3 + 4);
        float4 b3c = *(const float4*)(p3 + 8);

        a3[0]  += b3a.x + a1*r2a.x + a2*b1a.x;
        a3[1]  += b3a.y + a1*r2a.y + a2*b1a.y;
        a3[2]  += b3a.z + a1*r2a.z + a2*b1a.z;
        a3[3]  += b3a.w + a1*r2a.w + a2*b1a.w;
        a3[4]  += b3b.x + a1*r2b.x + a2*b1b.x;
        a3[5]  += b3b.y + a1*r2b.y + a2*b1b.y;
        a3[6]  += b3b.z + a1*r2b.z + a2*b1b.z;
        a3[7]  += b3b.w + a1*r2b.w + a2*b1b.w;
        a3[8]  += b3c.x + a1*r2c.x + a2*b1c.x;
        a3[9]  += b3c.y + a1*r2c.y + a2*b1c.y;
        a3[10] += b3c.z + a1*r2c.z + a2*b1c.z;
        a3[11] += b3c.w + a1*r2c.w + a2*b1c.w;
        a2 += b2s + a1 * b1j;     // uses OLD a1
        a1 += b1i;
    }

    if (j == 0) out[i] = a1;
    out[12 + tid] = a2;
    float* o3 = out + 156 + tid * 12;
    *(float4*)(o3)     = make_float4(a3[0], a3[1], a3[2], a3[3]);
    *(float4*)(o3 + 4) = make_float4(a3[4], a3[5], a3[6], a3[7]);
    *(float4*)(o3 + 8) = make_float4(a3[8], a3[9], a3[10], a3[11]);
}

// Level 1: 256 blocks, each merges 4 consecutive chunk sigs -> g_mid
__global__ __launch_bounds__(160) void sig_combine1_kernel()
{
    int tid = threadIdx.x;
    if (tid >= 144) return;
    combine_path(g_chunksig + (size_t)blockIdx.x * 4 * SIGC,
                 g_mid + (size_t)blockIdx.x * SIGC, 4, tid);
}

// Level 2: 64 blocks, each merges 4 mids -> g_sig
__global__ __launch_bounds__(160) void sig_combine2_kernel()
{
    int tid = threadIdx.x;
    if (tid >= 144) return;
    combine_path(g_mid + (size_t)blockIdx.x * 4 * SIGC,
                 g_sig + (size_t)blockIdx.x * SIGC, 4, tid);
}

// ---------------------------------------------------------------------------
// Kernel 3: out[b][o] = sigmoid( sig[b] . lin_w[o] + lin_b[o] )
// sig[b] = concat over g (contiguous in g_sig since bg = b*2+g). 3768 floats.
// ---------------------------------------------------------------------------
#define SIG2  (2 * SIGC)        // 3768
#define SIG2V (SIG2 / 4)        // 942 float4s

__global__ __launch_bounds__(256) void sig_out_kernel(
    const float* __restrict__ lin_w, const float* __restrict__ lin_b,
    float* __restrict__ out)
{
    int b = blockIdx.x;
    __shared__ __align__(16) float4 sh[SIG2V];
    const float4* sig = (const float4*)(g_sig + (size_t)b * SIG2);
    for (int idx = threadIdx.x; idx < SIG2V; idx += blockDim.x)
        sh[idx] = sig[idx];
    __syncthreads();

    int warp = threadIdx.x >> 5;
    int lane = threadIdx.x & 31;
    for (int o = warp; o < 32; o += 8) {
        const float4* wr = (const float4*)(lin_w + (size_t)o * SIG2);
        float acc0 = 0.f, acc1 = 0.f;
        // two independent FMA chains to hide FFMA latency
        for (int m = lane; m < SIG2V; m += 64) {
            float4 w = __ldg(wr + m);
            float4 s = sh[m];
            acc0 = fmaf(w.x, s.x, acc0);
            acc0 = fmaf(w.y, s.y, acc0);
            acc0 = fmaf(w.z, s.z, acc0);
            acc0 = fmaf(w.w, s.w, acc0);
            int m2 = m + 32;
            if (m2 < SIG2V) {
                float4 w2 = __ldg(wr + m2);
                float4 s2 = sh[m2];
                acc1 = fmaf(w2.x, s2.x, acc1);
                acc1 = fmaf(w2.y, s2.y, acc1);
                acc1 = fmaf(w2.z, s2.z, acc1);
                acc1 = fmaf(w2.w, s2.w, acc1);
            }
        }
        float acc = acc0 + acc1;
#pragma unroll
        for (int off = 16; off; off >>= 1)
            acc += __shfl_down_sync(0xffffffffu, acc, off);
        if (lane == 0) {
            float z = acc + lin_b[o];
            out[b * 32 + o] = 1.0f / (1.0f + expf(-z));
        }
    }
}

// ---------------------------------------------------------------------------
extern "C" void kernel_launch(void* const* d_in, const int* in_sizes, int n_in,
                              void* d_out, int out_size)
{
    const float* x     = (const float*)d_in[0];  // (32,1024,3)
    const float* aug_w = (const float*)d_in[1];  // (2,8,3)
    // d_in[2] = aug_b — unused (bias cancels in path increments)
    const float* lin_w = (const float*)d_in[3];  // (32, 3768)
    const float* lin_b = (const float*)d_in[4];  // (32,)
    float* out = (float*)d_out;                  // (32,32)

    sig_chunk_kernel<<<NBG * NCHUNK / CPB, 288>>>(x, aug_w);
    sig_combine1_kernel<<<NBG * 4, 160>>>();
    sig_combine2_kernel<<<NBG, 160>>>();
    sig_out_kernel<<<B_, 256>>>(lin_w, lin_b, out);
}

// round 6
// speedup vs baseline: 1.6267x; 1.2717x over previous
#include <cuda_runtime.h>
#include <math.h>

// Problem constants
#define B_      32
#define T_      1024
#define INCH    3
#define CD      12          // path channels: 1 time + 3 orig + 8 aug
#define SIGC    1884        // 12 + 144 + 1728
#define NBG     64          // B * G paths
#define NCHUNK  16
#define CH_STEPS 64
#define NSTEPS  1023
#define DT_     (1.0f/1023.0f)
#define CPB     2           // chunks per block in kernel 1

// Scratch (static device arrays — no allocation)
__device__ __align__(16) float g_chunksig[NBG * NCHUNK * SIGC];  // ~7.7 MB
__device__ __align__(16) float g_mid[NBG * 4 * SIGC];            // ~1.9 MB
__device__ __align__(16) float g_sig[NBG * SIGC];                // ~482 KB

typedef unsigned long long ull;

__device__ __forceinline__ ull pack2(float a, float b) {
    ull r;
    asm("mov.b64 %0, {%1,%2};" : "=l"(r) : "f"(a), "f"(b));
    return r;
}
__device__ __forceinline__ void ffma2(ull& d, ull a, ull b) {
    asm("fma.rn.f32x2 %0, %1, %2, %0;" : "+l"(d) : "l"(a), "l"(b));
}
union U64F2 { ull u; float2 f; };

// ---------------------------------------------------------------------------
// Kernel 1: per-chunk depth-3 signature. Collapsed per-step update:
//   S3[i][j][:] += (S2[i][j] + (S1[i] + d_i/3) * d_j/2) * d[:]   (6x FFMA2)
//   S2[i][j]    += (S1[i] + d_i/2) * d_j
//   S1[i]       += d_i
// 288 threads = 2 chunks x 144 (i,j) pairs, 9 full warps.
// ---------------------------------------------------------------------------
__global__ __launch_bounds__(288) void sig_chunk_kernel(
    const float* __restrict__ x, const float* __restrict__ aug_w)
{
    __shared__ __align__(16) float sh_d[CPB][CH_STEPS * CD];
    __shared__ float sh_w[CPB][24];

    int tid = threadIdx.x;
    int sub = (tid >= 144) ? 1 : 0;
    int wt  = tid - sub * 144;              // 0..143
    int chunk = blockIdx.x * CPB + sub;     // 0..1023
    int bg = chunk >> 4;                    // path id (b*2+g)
    int c  = chunk & 15;
    int b  = bg >> 1;
    int g  = bg & 1;
    int t0 = c * CH_STEPS;
    int L  = min(CH_STEPS, NSTEPS - t0);    // 64, last chunk per path 63

    if (wt < 24) sh_w[sub][wt] = aug_w[g * 24 + wt];
    __syncthreads();

    // increments: d[t] = [dt, dx0..2, W_g*dx]  (aug bias cancels)
    if (wt < L) {
        const float* xp = x + ((size_t)b * T_ + (t0 + wt)) * INCH;
        float dx0 = xp[3] - xp[0];
        float dx1 = xp[4] - xp[1];
        float dx2 = xp[5] - xp[2];
        float* dr = sh_d[sub] + wt * CD;
        dr[0] = DT_; dr[1] = dx0; dr[2] = dx1; dr[3] = dx2;
        const float* w = sh_w[sub];
#pragma unroll
        for (int e = 0; e < 8; e++)
            dr[4 + e] = w[e*3]*dx0 + w[e*3+1]*dx1 + w[e*3+2]*dx2;
    }
    __syncthreads();

    int i = wt / 12;
    int j = wt % 12;

    float s1 = 0.f, s2 = 0.f;
    ull s3p[6];
#pragma unroll
    for (int m = 0; m < 6; m++) s3p[m] = 0ull;

    const float* drbase = sh_d[sub];
#pragma unroll 4
    for (int t = 0; t < L; t++) {
        const float* dr = drbase + t * CD;
        const ulonglong2* q = (const ulonglong2*)dr;   // 16B-aligned (48B rows)
        ulonglong2 qa = q[0];
        ulonglong2 qb = q[1];
        ulonglong2 qc = q[2];
        float di = dr[i];
        float dj = dr[j];
        float c3 = fmaf(fmaf(di, (1.f/3.f), s1), 0.5f * dj, s2);
        ull cc = pack2(c3, c3);
        ffma2(s3p[0], cc, qa.x); ffma2(s3p[1], cc, qa.y);
        ffma2(s3p[2], cc, qb.x); ffma2(s3p[3], cc, qb.y);
        ffma2(s3p[4], cc, qc.x); ffma2(s3p[5], cc, qc.y);
        s2 = fmaf(fmaf(di, 0.5f, s1), dj, s2);
        s1 += di;
    }

    // Store chunk signature: [S1(12) | S2(144) | S3(1728)] signatory layout
    float* out = g_chunksig + (size_t)chunk * SIGC;
    if (j == 0) out[i] = s1;
    out[12 + wt] = s2;
    float* o3 = out + 156 + wt * 12;
    U64F2 u0, u1, u2, u3, u4, u5;
    u0.u = s3p[0]; u1.u = s3p[1]; u2.u = s3p[2];
    u3.u = s3p[3]; u4.u = s3p[4]; u5.u = s3p[5];
    *(float4*)(o3)     = make_float4(u0.f.x, u0.f.y, u1.f.x, u1.f.y);
    *(float4*)(o3 + 4) = make_float4(u2.f.x, u2.f.y, u3.f.x, u3.f.y);
    *(float4*)(o3 + 8) = make_float4(u4.f.x, u4.f.y, u5.f.x, u5.f.y);
}

// ---------------------------------------------------------------------------
// Chen combine of `nmerge` consecutive signatures (left-to-right):
//   C3 = A3 + B3 + A1 (x) B2 + A2 (x) B1 ; C2 = A2 + B2 + A1 (x) B1 ; C1 = A1+B1
// ---------------------------------------------------------------------------
__device__ __forceinline__ void combine_path(
    const float* __restrict__ base, float* __restrict__ out, int nmerge, int tid)
{
    int i = tid / 12;
    int j = tid % 12;

    float a1 = base[i];
    float a2 = base[12 + tid];
    float a3[12];
    {
        const float* p = base + 156 + tid * 12;
        float4 v0 = *(const float4*)p;
        float4 v1 = *(const float4*)(p + 4);
        float4 v2 = *(const float4*)(p + 8);
        a3[0]=v0.x; a3[1]=v0.y; a3[2]=v0.z;  a3[3]=v0.w;
        a3[4]=v1.x; a3[5]=v1.y; a3[6]=v1.z;  a3[7]=v1.w;
        a3[8]=v2.x; a3[9]=v2.y; a3[10]=v2.z; a3[11]=v2.w;
    }

    for (int c = 1; c < nmerge; c++) {
        const float* Bp = base + (size_t)c * SIGC;
        float4 b1a = *(const float4*)(Bp);
        float4 b1b = *(const float4*)(Bp + 4);
        float4 b1c = *(const float4*)(Bp + 8);
        float b1i = Bp[i];
        float b1j = Bp[j];
        float b2s = Bp[12 + tid];
        const float* r2 = Bp + 12 + j * 12;          // B2 row j
        float4 r2a = *(const float4*)(r2);
        float4 r2b = *(const float4*)(r2 + 4);
        float4 r2c = *(const float4*)(r2 + 8);
        const float* p3 = Bp + 156 + tid * 12;
        float4 b3a = *(const float4*)(p3);
        float4 b3b = *(const float4*)(p3 + 4);
        float4 b3c = *(const float4*)(p3 + 8);

        a3[0]  += b3a.x + a1*r2a.x + a2*b1a.x;
        a3[1]  += b3a.y + a1*r2a.y + a2*b1a.y;
        a3[2]  += b3a.z + a1*r2a.z + a2*b1a.z;
        a3[3]  += b3a.w + a1*r2a.w + a2*b1a.w;
        a3[4]  += b3b.x + a1*r2b.x + a2*b1b.x;
        a3[5]  += b3b.y + a1*r2b.y + a2*b1b.y;
        a3[6]  += b3b.z + a1*r2b.z + a2*b1b.z;
        a3[7]  += b3b.w + a1*r2b.w + a2*b1b.w;
        a3[8]  += b3c.x + a1*r2c.x + a2*b1c.x;
        a3[9]  += b3c.y + a1*r2c.y + a2*b1c.y;
        a3[10] += b3c.z + a1*r2c.z + a2*b1c.z;
        a3[11] += b3c.w + a1*r2c.w + a2*b1c.w;
        a2 += b2s + a1 * b1j;     // uses OLD a1
        a1 += b1i;
    }

    if (j == 0) out[i] = a1;
    out[12 + tid] = a2;
    float* o3 = out + 156 + tid * 12;
    *(float4*)(o3)     = make_float4(a3[0], a3[1], a3[2], a3[3]);
    *(float4*)(o3 + 4) = make_float4(a3[4], a3[5], a3[6], a3[7]);
    *(float4*)(o3 + 8) = make_float4(a3[8], a3[9], a3[10], a3[11]);
}

// Level 1: 256 blocks, each merges 4 consecutive chunk sigs -> g_mid
__global__ __launch_bounds__(160) void sig_combine1_kernel()
{
    int tid = threadIdx.x;
    if (tid >= 144) return;
    combine_path(g_chunksig + (size_t)blockIdx.x * 4 * SIGC,
                 g_mid + (size_t)blockIdx.x * SIGC, 4, tid);
}

// Level 2: 64 blocks, each merges 4 mids -> g_sig
__global__ __launch_bounds__(160) void sig_combine2_kernel()
{
    int tid = threadIdx.x;
    if (tid >= 144) return;
    combine_path(g_mid + (size_t)blockIdx.x * 4 * SIGC,
                 g_sig + (size_t)blockIdx.x * SIGC, 4, tid);
}

// ---------------------------------------------------------------------------
// Kernel 3: one block per output element (b,o):
//   out[b][o] = sigmoid( sig[b] . lin_w[o] + lin_b[o] )
// 1024 blocks x 128 threads = 4096 warps -> latency fully hidden.
// sig[b] = 3768 floats contiguous in g_sig (bg = b*2+g ordering).
// ---------------------------------------------------------------------------
#define SIG2  (2 * SIGC)        // 3768
#define SIG2V (SIG2 / 4)        // 942 float4s

__global__ __launch_bounds__(128) void sig_out_kernel(
    const float* __restrict__ lin_w, const float* __restrict__ lin_b,
    float* __restrict__ out)
{
    int b = blockIdx.x >> 5;
    int o = blockIdx.x & 31;
    int tid = threadIdx.x;

    const float4* wr = (const float4*)(lin_w + (size_t)o * SIG2);
    const float4* sg = (const float4*)(g_sig + (size_t)b * SIG2);

    // 942 float4s over 128 threads: 7 full strides + partial 8th
    float acc = 0.f;
#pragma unroll
    for (int it = 0; it < 8; it++) {
        int m = tid + it * 128;
        if (m < SIG2V) {
            float4 w = __ldg(wr + m);
            float4 s = __ldg(sg + m);
            acc = fmaf(w.x, s.x, acc);
            acc = fmaf(w.y, s.y, acc);
            acc = fmaf(w.z, s.z, acc);
            acc = fmaf(w.w, s.w, acc);
        }
    }

    // warp reduce
#pragma unroll
    for (int off = 16; off; off >>= 1)
        acc += __shfl_down_sync(0xffffffffu, acc, off);

    __shared__ float sh[4];
    int warp = tid >> 5;
    int lane = tid & 31;
    if (lane == 0) sh[warp] = acc;
    __syncthreads();

    if (tid == 0) {
        float z = sh[0] + sh[1] + sh[2] + sh[3] + lin_b[o];
        out[b * 32 + o] = 1.0f / (1.0f + expf(-z));
    }
}

// ---------------------------------------------------------------------------
extern "C" void kernel_launch(void* const* d_in, const int* in_sizes, int n_in,
                              void* d_out, int out_size)
{
    const float* x     = (const float*)d_in[0];  // (32,1024,3)
    const float* aug_w = (const float*)d_in[1];  // (2,8,3)
    // d_in[2] = aug_b — unused (bias cancels in path increments)
    const float* lin_w = (const float*)d_in[3];  // (32, 3768)
    const float* lin_b = (const float*)d_in[4];  // (32,)
    float* out = (float*)d_out;                  // (32,32)

    sig_chunk_kernel<<<NBG * NCHUNK / CPB, 288>>>(x, aug_w);
    sig_combine1_kernel<<<NBG * 4, 160>>>();
    sig_combine2_kernel<<<NBG, 160>>>();
    sig_out_kernel<<<B_ * 32, 128>>>(lin_w, lin_b, out);
}

// round 7
// speedup vs baseline: 2.0045x; 1.2323x over previous
#include <cuda_runtime.h>
#include <math.h>

// Problem constants
#define B_      32
#define T_      1024
#define INCH    3
#define CD      12          // path channels: 1 time + 3 orig + 8 aug
#define SIGC    1884        // 12 + 144 + 1728
#define SIGPAD  1888        // padded shared stride
#define NBG     64          // B * G paths
#define NCHUNK  16
#define CH_STEPS 64
#define NSTEPS  1023
#define DT_     (1.0f/1023.0f)

// Scratch (static device arrays — no allocation)
__device__ __align__(16) float g_mid[256 * SIGC];   // 4 per path
__device__ __align__(16) float g_sig[NBG * SIGC];

typedef unsigned long long ull;

__device__ __forceinline__ ull pack2(float a, float b) {
    ull r;
    asm("mov.b64 %0, {%1,%2};" : "=l"(r) : "f"(a), "f"(b));
    return r;
}
__device__ __forceinline__ void ffma2(ull& d, ull a, ull b) {
    asm("fma.rn.f32x2 %0, %1, %2, %0;" : "+l"(d) : "l"(a), "l"(b));
}
union U64F2 { ull u; float2 f; };

// ---------------------------------------------------------------------------
// Kernel 1: 4 chunks per block (72 threads each), fused level-1 Chen combine.
// Per-thread: i = wt/6, owns j0=2m, j1=2m+1 (m = wt%6).
// Per-step collapsed update (all packed f32x2):
//   u  = di/6 + s1/2 ;  c3pair = s2pair + u*djpair           (1 FFMA2)
//   S3[i][j][:] += c3_j * d[:]                               (12 FFMA2)
//   v  = s1 + di/2   ;  s2pair += v*djpair                   (1 FFMA2)
//   s1 += di
// ---------------------------------------------------------------------------
__global__ __launch_bounds__(288) void sig_chunk4_kernel(
    const float* __restrict__ x, const float* __restrict__ aug_w)
{
    __shared__ __align__(16) float sh_d[4][CH_STEPS * CD];   // 12.3 KB
    __shared__ __align__(16) float sh_sig[4][SIGPAD];        // 30.2 KB
    __shared__ float sh_w[4][24];

    int tid = threadIdx.x;
    int sub = tid / 72;
    int wt  = tid - sub * 72;               // 0..71
    int chunk = blockIdx.x * 4 + sub;       // 0..1023
    int bg = chunk >> 4;
    int c  = chunk & 15;
    int b  = bg >> 1;
    int g  = bg & 1;
    int t0 = c * CH_STEPS;
    int L  = min(CH_STEPS, NSTEPS - t0);    // 64, last chunk of path: 63

    if (wt < 24) sh_w[sub][wt] = aug_w[g * 24 + wt];
    __syncthreads();

    // increments: d[t] = [dt, dx0..2, W_g*dx]  (aug bias cancels)
    if (wt < L) {
        const float* xp = x + ((size_t)b * T_ + (t0 + wt)) * INCH;
        float dx0 = xp[3] - xp[0];
        float dx1 = xp[4] - xp[1];
        float dx2 = xp[5] - xp[2];
        float* dr = sh_d[sub] + wt * CD;
        dr[0] = DT_; dr[1] = dx0; dr[2] = dx1; dr[3] = dx2;
        const float* w = sh_w[sub];
#pragma unroll
        for (int e = 0; e < 8; e++)
            dr[4 + e] = w[e*3]*dx0 + w[e*3+1]*dx1 + w[e*3+2]*dx2;
    }
    __syncthreads();

    int i = wt / 6;
    int m = wt - i * 6;

    float s1 = 0.f;
    ull s2p = 0ull;
    ull s3a[6], s3b[6];
#pragma unroll
    for (int q = 0; q < 6; q++) { s3a[q] = 0ull; s3b[q] = 0ull; }

    const float* drbase = sh_d[sub];
#pragma unroll 2
    for (int t = 0; t < L; t++) {
        const float* dr = drbase + t * CD;
        const ulonglong2* qv = (const ulonglong2*)dr;
        ulonglong2 qa = qv[0];
        ulonglong2 qb = qv[1];
        ulonglong2 qc = qv[2];
        float di = dr[i];
        ull djp = *(const ull*)(dr + 2 * m);       // (d_{j0}, d_{j1})

        float u = fmaf(di, (1.f/6.f), 0.5f * s1);
        ull c3p = s2p;
        ffma2(c3p, pack2(u, u), djp);
        U64F2 cu; cu.u = c3p;
        ull cc0 = pack2(cu.f.x, cu.f.x);
        ull cc1 = pack2(cu.f.y, cu.f.y);

        ffma2(s3a[0], cc0, qa.x); ffma2(s3a[1], cc0, qa.y);
        ffma2(s3a[2], cc0, qb.x); ffma2(s3a[3], cc0, qb.y);
        ffma2(s3a[4], cc0, qc.x); ffma2(s3a[5], cc0, qc.y);
        ffma2(s3b[0], cc1, qa.x); ffma2(s3b[1], cc1, qa.y);
        ffma2(s3b[2], cc1, qb.x); ffma2(s3b[3], cc1, qb.y);
        ffma2(s3b[4], cc1, qc.x); ffma2(s3b[5], cc1, qc.y);

        float v = fmaf(di, 0.5f, s1);
        ffma2(s2p, pack2(v, v), djp);
        s1 += di;
    }

    // Store this chunk's signature into shared staging (signatory layout)
    {
        float* out = sh_sig[sub];
        if (m == 0) out[i] = s1;
        U64F2 s2u; s2u.u = s2p;
        out[12 + i*12 + 2*m]     = s2u.f.x;
        out[12 + i*12 + 2*m + 1] = s2u.f.y;
        float* o3 = out + 156 + (i*12 + 2*m) * 12;   // row j0, then row j1
        U64F2 w0, w1, w2, w3, w4, w5;
        w0.u = s3a[0]; w1.u = s3a[1]; w2.u = s3a[2];
        w3.u = s3a[3]; w4.u = s3a[4]; w5.u = s3a[5];
        *(float4*)(o3)     = make_float4(w0.f.x, w0.f.y, w1.f.x, w1.f.y);
        *(float4*)(o3 + 4) = make_float4(w2.f.x, w2.f.y, w3.f.x, w3.f.y);
        *(float4*)(o3 + 8) = make_float4(w4.f.x, w4.f.y, w5.f.x, w5.f.y);
        w0.u = s3b[0]; w1.u = s3b[1]; w2.u = s3b[2];
        w3.u = s3b[3]; w4.u = s3b[4]; w5.u = s3b[5];
        *(float4*)(o3 + 12) = make_float4(w0.f.x, w0.f.y, w1.f.x, w1.f.y);
        *(float4*)(o3 + 16) = make_float4(w2.f.x, w2.f.y, w3.f.x, w3.f.y);
        *(float4*)(o3 + 20) = make_float4(w4.f.x, w4.f.y, w5.f.x, w5.f.y);
    }
    __syncthreads();

    // Fused level-1 Chen combine (4 chunks -> 1), threads 0..143
    if (tid < 144) {
        int ci = tid / 12;
        int cj = tid - ci * 12;

        float a1 = sh_sig[0][ci];
        float a2 = sh_sig[0][12 + tid];
        float a3[12];
        {
            const float* p = sh_sig[0] + 156 + tid * 12;
            float4 v0 = *(const float4*)p;
            float4 v1 = *(const float4*)(p + 4);
            float4 v2 = *(const float4*)(p + 8);
            a3[0]=v0.x; a3[1]=v0.y; a3[2]=v0.z;  a3[3]=v0.w;
            a3[4]=v1.x; a3[5]=v1.y; a3[6]=v1.z;  a3[7]=v1.w;
            a3[8]=v2.x; a3[9]=v2.y; a3[10]=v2.z; a3[11]=v2.w;
        }

#pragma unroll
        for (int cc = 1; cc < 4; cc++) {
            const float* Bp = sh_sig[cc];
            float4 b1a = *(const float4*)(Bp);
            float4 b1b = *(const float4*)(Bp + 4);
            float4 b1c = *(const float4*)(Bp + 8);
            float b1i = Bp[ci];
            float b1j = Bp[cj];
            float b2s = Bp[12 + tid];
            const float* r2 = Bp + 12 + cj * 12;
            float4 r2a = *(const float4*)(r2);
            float4 r2b = *(const float4*)(r2 + 4);
            float4 r2c = *(const float4*)(r2 + 8);
            const float* p3 = Bp + 156 + tid * 12;
            float4 b3a = *(const float4*)(p3);
            float4 b3b = *(const float4*)(p3 + 4);
            float4 b3c = *(const float4*)(p3 + 8);

            a3[0]  += b3a.x + a1*r2a.x + a2*b1a.x;
            a3[1]  += b3a.y + a1*r2a.y + a2*b1a.y;
            a3[2]  += b3a.z + a1*r2a.z + a2*b1a.z;
            a3[3]  += b3a.w + a1*r2a.w + a2*b1a.w;
            a3[4]  += b3b.x + a1*r2b.x + a2*b1b.x;
            a3[5]  += b3b.y + a1*r2b.y + a2*b1b.y;
            a3[6]  += b3b.z + a1*r2b.z + a2*b1b.z;
            a3[7]  += b3b.w + a1*r2b.w + a2*b1b.w;
            a3[8]  += b3c.x + a1*r2c.x + a2*b1c.x;
            a3[9]  += b3c.y + a1*r2c.y + a2*b1c.y;
            a3[10] += b3c.z + a1*r2c.z + a2*b1c.z;
            a3[11] += b3c.w + a1*r2c.w + a2*b1c.w;
            a2 += b2s + a1 * b1j;     // uses OLD a1
            a1 += b1i;
        }

        float* out = g_mid + (size_t)blockIdx.x * SIGC;
        if (cj == 0) out[ci] = a1;
        out[12 + tid] = a2;
        float* o3 = out + 156 + tid * 12;
        *(float4*)(o3)     = make_float4(a3[0], a3[1], a3[2], a3[3]);
        *(float4*)(o3 + 4) = make_float4(a3[4], a3[5], a3[6], a3[7]);
        *(float4*)(o3 + 8) = make_float4(a3[8], a3[9], a3[10], a3[11]);
    }
}

// ---------------------------------------------------------------------------
// Kernel 2: level-2 Chen combine (4 mids -> final signature per path)
// ---------------------------------------------------------------------------
__global__ __launch_bounds__(160) void sig_combine2_kernel()
{
    int tid = threadIdx.x;
    if (tid >= 144) return;
    int i = tid / 12;
    int j = tid - i * 12;

    const float* base = g_mid + (size_t)blockIdx.x * 4 * SIGC;

    float a1 = base[i];
    float a2 = base[12 + tid];
    float a3[12];
    {
        const float* p = base + 156 + tid * 12;
        float4 v0 = *(const float4*)p;
        float4 v1 = *(const float4*)(p + 4);
        float4 v2 = *(const float4*)(p + 8);
        a3[0]=v0.x; a3[1]=v0.y; a3[2]=v0.z;  a3[3]=v0.w;
        a3[4]=v1.x; a3[5]=v1.y; a3[6]=v1.z;  a3[7]=v1.w;
        a3[8]=v2.x; a3[9]=v2.y; a3[10]=v2.z; a3[11]=v2.w;
    }

#pragma unroll
    for (int c = 1; c < 4; c++) {
        const float* Bp = base + (size_t)c * SIGC;
        float4 b1a = *(const float4*)(Bp);
        float4 b1b = *(const float4*)(Bp + 4);
        float4 b1c = *(const float4*)(Bp + 8);
        float b1i = Bp[i];
        float b1j = Bp[j];
        float b2s = Bp[12 + tid];
        const float* r2 = Bp + 12 + j * 12;
        float4 r2a = *(const float4*)(r2);
        float4 r2b = *(const float4*)(r2 + 4);
        float4 r2c = *(const float4*)(r2 + 8);
        const float* p3 = Bp + 156 + tid * 12;
        float4 b3a = *(const float4*)(p3);
        float4 b3b = *(const float4*)(p3 + 4);
        float4 b3c = *(const float4*)(p3 + 8);

        a3[0]  += b3a.x + a1*r2a.x + a2*b1a.x;
        a3[1]  += b3a.y + a1*r2a.y + a2*b1a.y;
        a3[2]  += b3a.z + a1*r2a.z + a2*b1a.z;
        a3[3]  += b3a.w + a1*r2a.w + a2*b1a.w;
        a3[4]  += b3b.x + a1*r2b.x + a2*b1b.x;
        a3[5]  += b3b.y + a1*r2b.y + a2*b1b.y;
        a3[6]  += b3b.z + a1*r2b.z + a2*b1b.z;
        a3[7]  += b3b.w + a1*r2b.w + a2*b1b.w;
        a3[8]  += b3c.x + a1*r2c.x + a2*b1c.x;
        a3[9]  += b3c.y + a1*r2c.y + a2*b1c.y;
        a3[10] += b3c.z + a1*r2c.z + a2*b1c.z;
        a3[11] += b3c.w + a1*r2c.w + a2*b1c.w;
        a2 += b2s + a1 * b1j;
        a1 += b1i;
    }

    float* out = g_sig + (size_t)blockIdx.x * SIGC;
    if (j == 0) out[i] = a1;
    out[12 + tid] = a2;
    float* o3 = out + 156 + tid * 12;
    *(float4*)(o3)     = make_float4(a3[0], a3[1], a3[2], a3[3]);
    *(float4*)(o3 + 4) = make_float4(a3[4], a3[5], a3[6], a3[7]);
    *(float4*)(o3 + 8) = make_float4(a3[8], a3[9], a3[10], a3[11]);
}

// ---------------------------------------------------------------------------
// Kernel 3: one block per output element (b,o):
//   out[b][o] = sigmoid( sig[b] . lin_w[o] + lin_b[o] )
// ---------------------------------------------------------------------------
#define SIG2  (2 * SIGC)        // 3768
#define SIG2V (SIG2 / 4)        // 942 float4s

__global__ __launch_bounds__(128) void sig_out_kernel(
    const float* __restrict__ lin_w, const float* __restrict__ lin_b,
    float* __restrict__ out)
{
    int b = blockIdx.x >> 5;
    int o = blockIdx.x & 31;
    int tid = threadIdx.x;

    const float4* wr = (const float4*)(lin_w + (size_t)o * SIG2);
    const float4* sg = (const float4*)(g_sig + (size_t)b * SIG2);

    float acc = 0.f;
#pragma unroll
    for (int it = 0; it < 8; it++) {
        int m = tid + it * 128;
        if (m < SIG2V) {
            float4 w = __ldg(wr + m);
            float4 s = __ldg(sg + m);
            acc = fmaf(w.x, s.x, acc);
            acc = fmaf(w.y, s.y, acc);
            acc = fmaf(w.z, s.z, acc);
            acc = fmaf(w.w, s.w, acc);
        }
    }

#pragma unroll
    for (int off = 16; off; off >>= 1)
        acc += __shfl_down_sync(0xffffffffu, acc, off);

    __shared__ float sh[4];
    int warp = tid >> 5;
    int lane = tid & 31;
    if (lane == 0) sh[warp] = acc;
    __syncthreads();

    if (tid == 0) {
        float z = sh[0] + sh[1] + sh[2] + sh[3] + lin_b[o];
        out[b * 32 + o] = 1.0f / (1.0f + expf(-z));
    }
}

// ---------------------------------------------------------------------------
extern "C" void kernel_launch(void* const* d_in, const int* in_sizes, int n_in,
                              void* d_out, int out_size)
{
    const float* x     = (const float*)d_in[0];  // (32,1024,3)
    const float* aug_w = (const float*)d_in[1];  // (2,8,3)
    // d_in[2] = aug_b — unused (bias cancels in path increments)
    const float* lin_w = (const float*)d_in[3];  // (32, 3768)
    const float* lin_b = (const float*)d_in[4];  // (32,)
    float* out = (float*)d_out;                  // (32,32)

    sig_chunk4_kernel<<<256, 288>>>(x, aug_w);
    sig_combine2_kernel<<<NBG, 160>>>();
    sig_out_kernel<<<B_ * 32, 128>>>(lin_w, lin_b, out);
}